// round 17
// baseline (speedup 1.0000x reference)
#include <cuda_runtime.h>
#include <cstdint>
#include <math.h>

#define B_     4
#define NCH    32
#define T_FULL 65536
#define T_IN   8192
#define L_     256
#define HOP_   256
#define H_     64
#define KC_    24576

// ---- scratch (device globals; no allocation allowed) ----
__device__ float g_H [B_*NCH*T_FULL];   // hidden state buffer A
__device__ float g_C [B_*NCH*T_FULL];   // hidden state buffer B (double-buffer)
__device__ float g_F0[B_*H_*L_];
__device__ float g_KT[B_*L_*KC_];       // predicted kernels [n=b*L+l][kc]
__device__ float g_BS[B_*256*L_];       // predicted biases [b][bc][l]

__device__ __forceinline__ float lrelu(float x){ return x >= 0.f ? x : 0.2f*x; }

// ---- packed f32x2 helpers ----
__device__ __forceinline__ uint64_t pack2f(float lo, float hi){
    uint64_t r; asm("mov.b64 %0, {%1, %2};" : "=l"(r) : "f"(lo), "f"(hi)); return r;
}
__device__ __forceinline__ uint64_t bcast2f(float x){ return pack2f(x, x); }
__device__ __forceinline__ void fma2(uint64_t& d, uint64_t a, uint64_t b){
    asm("fma.rn.f32x2 %0, %1, %2, %0;" : "+l"(d) : "l"(a), "l"(b));
}
__device__ __forceinline__ float2 unpack2f(uint64_t v){
    float2 r; asm("mov.b64 {%0, %1}, %2;" : "=f"(r.x), "=f"(r.y) : "l"(v)); return r;
}

// ============================================================
// K1: conv_transpose1d  (stride 8, K=16, pad 4) -> g_H
// ============================================================
__global__ void k_convT(const float* __restrict__ x, const float* __restrict__ w,
                        const float* __restrict__ bias){
    int b  = blockIdx.y;
    int t0 = blockIdx.x * 256;
    int tid = threadIdx.x;
    int r = tid & 7, o = tid >> 3;
    __shared__ float xs[NCH*36];
    const float* xb = x + b*NCH*T_IN;
    int jbase = t0/8 - 1;
    for (int idx = tid; idx < NCH*34; idx += 256){
        int c = idx / 34, p = idx % 34;
        int j = jbase + p;
        xs[c*36 + p] = (j >= 0 && j < T_IN) ? xb[c*T_IN + j] : 0.f;
    }
    __syncthreads();
    float acc[32];
    float bv = bias[o];
    #pragma unroll
    for (int s = 0; s < 32; s++) acc[s] = bv;
    int off = (r + 4) & 7;
    int e   = (off >= 4) ? 1 : 0;
    for (int i = 0; i < NCH; i++){
        float w1 = w[(i*32 + o)*16 + r];
        float w2 = w[(i*32 + o)*16 + r + 8];
        const float* xr = &xs[i*36 + e];
        float vp = xr[0];
        #pragma unroll
        for (int s = 0; s < 32; s++){
            float v = xr[s + 1];
            acc[s] += w1*v + w2*vp;
            vp = v;
        }
    }
    float* out = &g_H[(b*NCH + o)*T_FULL];
    #pragma unroll
    for (int s = 0; s < 32; s++) out[t0 + off + 8*s] = acc[s];
}

// ============================================================
// K2: FUSED kernel predictor, L-tile 16 (grid B x 16).
// Buffer p in [0,32) <-> global l = l0-8+p, stride 36, stored
// at q=p+2. Spec conv valid all p; conv n valid [n, 31-n];
// final [6,25] covers needed [8,23].
// ============================================================
#define PRED_SMEM ((100*36 + 64*36 + 64*36 + 16000)*4)

__device__ __forceinline__ void pred_conv3(
    const float* src, float* dst, const float* rsd, float* wbuf,
    const float* __restrict__ wsrc, const float* __restrict__ bsrc,
    int plo, int phi, int l0, int hq, int pb, int tid){
    __syncthreads();
    for (int idx = tid; idx < 64*192; idx += 256){
        int h = idx/192, ck = idx%192;
        wbuf[ck*64 + h] = wsrc[h*192 + ck];
    }
    __syncthreads();
    uint64_t acc[2][2];
    #pragma unroll
    for (int m = 0; m < 2; m++){
        uint64_t bp = pack2f(bsrc[hq*4 + 2*m], bsrc[hq*4 + 2*m + 1]);
        acc[m][0] = bp; acc[m][1] = bp;
    }
    for (int c = 0; c < 64; c++){
        float xv[4];
        #pragma unroll
        for (int m = 0; m < 4; m++) xv[m] = src[c*36 + pb + 1 + m];
        #pragma unroll
        for (int k = 0; k < 3; k++){
            ulonglong2 wp = *(const ulonglong2*)&wbuf[(c*3 + k)*64 + hq*4];
            #pragma unroll
            for (int j = 0; j < 2; j++){
                uint64_t xb = bcast2f(xv[j + k]);
                fma2(acc[0][j], wp.x, xb);
                fma2(acc[1][j], wp.y, xb);
            }
        }
    }
    #pragma unroll
    for (int m = 0; m < 2; m++)
    #pragma unroll
    for (int j = 0; j < 2; j++){
        int p = pb + j;
        if (p >= plo && p <= phi){
            int gl = l0 - 8 + p;
            bool ok = (gl >= 0 && gl < L_);
            float2 u = unpack2f(acc[m][j]);
            int ch0 = hq*4 + 2*m;
            float v0 = lrelu(u.x), v1 = lrelu(u.y);
            if (rsd){ v0 += rsd[ch0*36 + p + 2]; v1 += rsd[(ch0+1)*36 + p + 2]; }
            dst[ch0*36 + p + 2]     = ok ? v0 : 0.f;
            dst[(ch0+1)*36 + p + 2] = ok ? v1 : 0.f;
        }
    }
}

__global__ void __launch_bounds__(256)
k_pred(const float* __restrict__ spec,
       const float* __restrict__ kp_w, const float* __restrict__ kp_b,
       const float* __restrict__ rb_w1, const float* __restrict__ rb_b1,
       const float* __restrict__ rb_w2, const float* __restrict__ rb_b2){
    extern __shared__ float sm[];
    float* sspec = sm;                 // 100 x 36
    float* bufA  = sm + 100*36;        // 64 x 36
    float* bufB  = bufA + 64*36;
    float* wbuf  = bufB + 64*36;       // 16000
    int b = blockIdx.x, ls = blockIdx.y;
    int l0 = ls*16;
    int tid = threadIdx.x;
    int hq = tid >> 4;                 // 16 groups of 4 channels
    int pb = (tid & 15) * 2;           // 16 groups of 2 positions

    // stage spec: q in [0,36) <-> gl = l0-10+q
    const float* sp = spec + b*100*L_;
    for (int idx = tid; idx < 100*36; idx += 256){
        int c = idx/36, q = idx%36;
        int gl = l0 - 10 + q;
        sspec[c*36 + q] = (gl >= 0 && gl < L_) ? sp[c*L_ + gl] : 0.f;
    }
    // --- spec conv (100->64, K=5, pad 2): valid all p in [0,32) ---
    uint64_t acc[2][2];
    #pragma unroll
    for (int m = 0; m < 2; m++){
        uint64_t bp = pack2f(kp_b[hq*4 + 2*m], kp_b[hq*4 + 2*m + 1]);
        acc[m][0] = bp; acc[m][1] = bp;
    }
    for (int chunk = 0; chunk < 2; chunk++){
        __syncthreads();
        for (int idx = tid; idx < 16000; idx += 256){
            int h = idx/250, ck = idx%250;
            wbuf[ck*64 + h] = kp_w[h*500 + chunk*250 + ck];
        }
        __syncthreads();
        for (int c2 = 0; c2 < 50; c2++){
            int c = chunk*50 + c2;
            float xv[6];
            #pragma unroll
            for (int m = 0; m < 6; m++) xv[m] = sspec[c*36 + pb + m];
            #pragma unroll
            for (int k = 0; k < 5; k++){
                ulonglong2 wp = *(const ulonglong2*)&wbuf[(c2*5 + k)*64 + hq*4];
                #pragma unroll
                for (int j = 0; j < 2; j++){
                    uint64_t xb = bcast2f(xv[j + k]);
                    fma2(acc[0][j], wp.x, xb);
                    fma2(acc[1][j], wp.y, xb);
                }
            }
        }
    }
    #pragma unroll
    for (int m = 0; m < 2; m++)
    #pragma unroll
    for (int j = 0; j < 2; j++){
        int p = pb + j;
        int gl = l0 - 8 + p;
        bool ok = (gl >= 0 && gl < L_);
        float2 u = unpack2f(acc[m][j]);
        int ch0 = hq*4 + 2*m;
        bufA[ch0*36 + p + 2]     = ok ? u.x : 0.f;
        bufA[(ch0+1)*36 + p + 2] = ok ? u.y : 0.f;
    }
    // --- 3 residual blocks ---
    #pragma unroll 1
    for (int i = 0; i < 3; i++){
        pred_conv3(bufA, bufB, nullptr, wbuf, rb_w1 + i*12288, rb_b1 + i*64,
                   2*i+1, 30-2*i, l0, hq, pb, tid);
        pred_conv3(bufB, bufA, bufA,    wbuf, rb_w2 + i*12288, rb_b2 + i*64,
                   2*i+2, 29-2*i, l0, hq, pb, tid);
    }
    __syncthreads();
    // final store: p in [8,23] <-> l = l0..l0+15
    #pragma unroll
    for (int m = 0; m < 2; m++)
    #pragma unroll
    for (int j = 0; j < 2; j++){
        int p = pb + j;
        if (p >= 8 && p <= 23){
            int l = l0 - 8 + p;
            int ch0 = hq*4 + 2*m;
            g_F0[(b*H_ + ch0    )*L_ + l] = bufA[ch0*36 + p + 2];
            g_F0[(b*H_ + ch0 + 1)*L_ + l] = bufA[(ch0+1)*36 + p + 2];
        }
    }
}

// ============================================================
// K5: kern conv GEMM (f32x2), tile 128(kc) x 64(n), double-
// buffered. 2 tail block-rows -> bias conv g_BS.
// ============================================================
__global__ void __launch_bounds__(256)
k_kern_gemm(const float* __restrict__ A, const float* __restrict__ Ab,
            const float* __restrict__ Bw, const float* __restrict__ Bb){
    int kc0 = blockIdx.x * 128;
    bool is_bias = (kc0 >= KC_);
    int n0  = blockIdx.y * 64;
    int b   = n0 / L_;
    int l0w = n0 % L_;
    int tid = threadIdx.x;
    int warp = tid >> 5, lane = tid & 31;
    int ty = (warp << 1) | (lane >> 4);
    int tx = lane & 15;
    __shared__ __align__(16) float As[2][16][128];
    __shared__ __align__(16) float Xs[2][16][68];
    const float* F = &g_F0[b*H_*L_];
    const float* Arow_base = is_bias ? Bw : A;
    const float* bias_base = is_bias ? Bb : Ab;
    int row_off = is_bias ? (kc0 - KC_) : kc0;

    uint64_t acc[4][4];
    #pragma unroll
    for (int m = 0; m < 4; m++){
        uint64_t bp = pack2f(bias_base[row_off + ty*8 + 2*m],
                             bias_base[row_off + ty*8 + 2*m + 1]);
        #pragma unroll
        for (int j = 0; j < 4; j++) acc[m][j] = bp;
    }
    int arow = tid >> 1, ac0 = (tid & 1) * 8;
    int xrr = tid >> 4, xc0 = (tid & 15) * 4;
    const float* Aptr = &Arow_base[(row_off + arow)*192 + ac0];

    {
        float4 v0 = *(const float4*)(Aptr);
        float4 v1 = *(const float4*)(Aptr + 4);
        As[0][ac0+0][arow] = v0.x; As[0][ac0+1][arow] = v0.y;
        As[0][ac0+2][arow] = v0.z; As[0][ac0+3][arow] = v0.w;
        As[0][ac0+4][arow] = v1.x; As[0][ac0+5][arow] = v1.y;
        As[0][ac0+6][arow] = v1.z; As[0][ac0+7][arow] = v1.w;
        int hh = xrr/3, k = xrr%3;
        #pragma unroll
        for (int q = 0; q < 4; q++){
            int t = l0w + xc0 + q + k - 1;
            Xs[0][xrr][xc0+q] = (t >= 0 && t < L_) ? F[hh*L_ + t] : 0.f;
        }
    }
    __syncthreads();

    #pragma unroll 1
    for (int bk = 0; bk < 12; bk++){
        int cur = bk & 1, nxt = cur ^ 1;
        if (bk < 11){
            int r0 = (bk + 1)*16;
            float4 v0 = *(const float4*)(Aptr + r0);
            float4 v1 = *(const float4*)(Aptr + r0 + 4);
            As[nxt][ac0+0][arow] = v0.x; As[nxt][ac0+1][arow] = v0.y;
            As[nxt][ac0+2][arow] = v0.z; As[nxt][ac0+3][arow] = v0.w;
            As[nxt][ac0+4][arow] = v1.x; As[nxt][ac0+5][arow] = v1.y;
            As[nxt][ac0+6][arow] = v1.z; As[nxt][ac0+7][arow] = v1.w;
            int r = r0 + xrr;
            int hh = r/3, k = r%3;
            #pragma unroll
            for (int q = 0; q < 4; q++){
                int t = l0w + xc0 + q + k - 1;
                Xs[nxt][xrr][xc0+q] = (t >= 0 && t < L_) ? F[hh*L_ + t] : 0.f;
            }
        }
        #pragma unroll
        for (int kk = 0; kk < 16; kk++){
            ulonglong2 aA = *(const ulonglong2*)&As[cur][kk][ty*8];
            ulonglong2 aB = *(const ulonglong2*)&As[cur][kk][ty*8 + 4];
            uint64_t a2[4] = {aA.x, aA.y, aB.x, aB.y};
            float4 xv = *(const float4*)&Xs[cur][kk][tx*4];
            uint64_t xb[4] = {bcast2f(xv.x), bcast2f(xv.y), bcast2f(xv.z), bcast2f(xv.w)};
            #pragma unroll
            for (int j = 0; j < 4; j++)
                #pragma unroll
                for (int m = 0; m < 4; m++)
                    fma2(acc[m][j], a2[m], xb[j]);
        }
        __syncthreads();
    }
    if (!is_bias){
        #pragma unroll
        for (int j = 0; j < 4; j++){
            int n = n0 + tx*4 + j;
            #pragma unroll
            for (int m = 0; m < 4; m++){
                float2 p = unpack2f(acc[m][j]);
                *(float2*)&g_KT[n*KC_ + kc0 + ty*8 + 2*m] = p;
            }
        }
    } else {
        #pragma unroll
        for (int j = 0; j < 4; j++){
            int l = l0w + tx*4 + j;
            #pragma unroll
            for (int m = 0; m < 4; m++){
                float2 p = unpack2f(acc[m][j]);
                int bc = row_off + ty*8 + 2*m;
                g_BS[(b*256 + bc    )*L_ + l] = p.x;
                g_BS[(b*256 + bc + 1)*L_ + l] = p.y;
            }
        }
    }
}

// ============================================================
// K7+K8 FUSED (R13-best version, 256 threads): lrelu -> dilated
// conv -> lrelu (smem sc) -> LVC + bias + gating + residual.
// Boundary samples (t=-1 at l=0, t=T at l=255) forced to 0.
// ============================================================
#define FUSED_SMEM ((32*312 + 3072 + 32*264 + 6144)*4)
template<int D>
__global__ void __launch_bounds__(256)
k_fused(int layer, const float* __restrict__ w, const float* __restrict__ bias,
        float* __restrict__ outp){
    extern __shared__ float sm[];
    float* sx  = sm;                    // 32 x 312: lrelu(Hin) window
    float* ws  = sm + 32*312;           // [k][i][o] 3072
    float* sc  = ws + 3072;             // 32 x 264 (258 used): conv out
    float* ksh = sc + 32*264;           // [k][c][o] 6144
    int b = blockIdx.y, l = blockIdx.x;
    int tid = threadIdx.x;
    int tseg = l*HOP_;
    const float* Hin  = (layer & 1) ? g_C : g_H;
    float* Hout = outp ? outp : ((layer & 1) ? g_H : g_C);
    const float* Hb = &Hin[b*NCH*T_FULL];

    const int W2 = 258 + 2*D;
    for (int idx = tid; idx < NCH*W2; idx += 256){
        int c = idx / W2, q = idx % W2;
        int t = tseg - 1 - D + q;
        sx[c*312 + q] = (t >= 0 && t < T_FULL) ? lrelu(Hb[c*T_FULL + t]) : 0.f;
    }
    for (int idx = tid; idx < 3072; idx += 256){
        int o = idx / 96, rem = idx % 96;
        int i = rem / 3, k = rem % 3;
        ws[k*1024 + i*32 + o] = w[idx];
    }
    const float* KTb = &g_KT[(b*L_ + l)*KC_ + layer*6144];
    const float4* K4 = (const float4*)KTb;
    for (int i4 = tid; i4 < 1536; i4 += 256){
        float4 v = K4[i4];
        float vv[4] = {v.x, v.y, v.z, v.w};
        int base = i4*4;
        #pragma unroll
        for (int e = 0; e < 4; e++){
            int idx = base + e;
            int c = idx / 192, rem = idx % 192;
            int o = rem / 3, k = rem % 3;
            ksh[k*2048 + c*64 + o] = vv[e];
        }
    }
    __syncthreads();

    // --- dconv phase 1: sc[o][p] for p in [0,256), thread = 4 ch x 8 p ---
    {
        int o0 = (tid >> 5) * 4;
        int p0 = (tid & 31) * 8;
        uint64_t acc[2][8];
        #pragma unroll
        for (int m = 0; m < 2; m++){
            uint64_t bp = pack2f(bias[o0 + 2*m], bias[o0 + 2*m + 1]);
            #pragma unroll
            for (int j = 0; j < 8; j++) acc[m][j] = bp;
        }
        for (int i = 0; i < NCH; i++){
            const float* xr = &sx[i*312 + p0];
            #pragma unroll
            for (int k = 0; k < 3; k++){
                ulonglong2 wp = *(const ulonglong2*)&ws[k*1024 + i*32 + o0];
                #pragma unroll
                for (int j = 0; j < 8; j++){
                    uint64_t xb = bcast2f(xr[j + k*D]);
                    fma2(acc[0][j], wp.x, xb);
                    fma2(acc[1][j], wp.y, xb);
                }
            }
        }
        #pragma unroll
        for (int cc = 0; cc < 4; cc++)
            #pragma unroll
            for (int j = 0; j < 8; j++){
                float2 u = unpack2f(acc[cc>>1][j]);
                float v = lrelu((cc & 1) ? u.y : u.x);
                if (l == 0 && p0 + j == 0) v = 0.f;   // LVC zero-pad t=-1
                sc[(o0 + cc)*264 + p0 + j] = v;
            }
    }
    // --- dconv phase 2: p = 256, 257 (64 values, scalar, warps 0-1) ---
    if (tid < 64){
        int ch = tid >> 1, p = 256 + (tid & 1);
        float acc = bias[ch];
        for (int i = 0; i < NCH; i++){
            #pragma unroll
            for (int k = 0; k < 3; k++)
                acc += ws[k*1024 + i*32 + ch] * sx[i*312 + p + k*D];
        }
        float v = lrelu(acc);
        if (l == L_ - 1 && p == 257) v = 0.f;         // LVC zero-pad t=T
        sc[ch*264 + p] = v;
    }
    __syncthreads();

    // --- LVC + gate + residual: thread = 4 ch x 8 samples ---
    int o0 = (tid >> 5) * 4;
    int s0 = (tid & 31) * 8;
    const float* Bb = &g_BS[(b*256 + layer*64)*L_];
    uint64_t accL[2][8], accH[2][8];
    #pragma unroll
    for (int m = 0; m < 2; m++){
        uint64_t bl = pack2f(Bb[(o0 + 2*m)*L_ + l],      Bb[(o0 + 2*m + 1)*L_ + l]);
        uint64_t bh = pack2f(Bb[(o0 + 2*m + 32)*L_ + l], Bb[(o0 + 2*m + 33)*L_ + l]);
        #pragma unroll
        for (int j = 0; j < 8; j++){ accL[m][j] = bl; accH[m][j] = bh; }
    }
    for (int c = 0; c < NCH; c++){
        const float* xr = &sc[c*264 + s0];
        float4 xa = *(const float4*)xr;
        float4 xbv = *(const float4*)(xr + 4);
        float2 xc = *(const float2*)(xr + 8);
        float xw[10] = {xa.x, xa.y, xa.z, xa.w, xbv.x, xbv.y, xbv.z, xbv.w, xc.x, xc.y};
        #pragma unroll
        for (int k = 0; k < 3; k++){
            ulonglong2 wl = *(const ulonglong2*)&ksh[k*2048 + c*64 + o0];
            ulonglong2 wh = *(const ulonglong2*)&ksh[k*2048 + c*64 + o0 + 32];
            #pragma unroll
            for (int j = 0; j < 8; j++){
                uint64_t x = bcast2f(xw[j + k]);
                fma2(accL[0][j], wl.x, x);
                fma2(accL[1][j], wl.y, x);
                fma2(accH[0][j], wh.x, x);
                fma2(accH[1][j], wh.y, x);
            }
        }
    }
    #pragma unroll
    for (int cc = 0; cc < 4; cc++){
        int oc = o0 + cc;
        const float* Hrow = &Hb[oc*T_FULL + tseg + s0];
        float4 r0 = *(const float4*)Hrow;
        float4 r1 = *(const float4*)(Hrow + 4);
        float rr[8] = {r0.x, r0.y, r0.z, r0.w, r1.x, r1.y, r1.z, r1.w};
        float tmp[8];
        #pragma unroll
        for (int j = 0; j < 8; j++){
            float2 uL = unpack2f(accL[cc>>1][j]);
            float2 uH = unpack2f(accH[cc>>1][j]);
            float aL = (cc & 1) ? uL.y : uL.x;
            float aH = (cc & 1) ? uH.y : uH.x;
            float sg = 1.f / (1.f + __expf(-aL));
            float th = tanhf(aH);
            tmp[j] = sg*th + rr[j];
        }
        float* dst = &Hout[(b*NCH + oc)*T_FULL + tseg + s0];
        *(float4*)dst     = make_float4(tmp[0], tmp[1], tmp[2], tmp[3]);
        *(float4*)(dst+4) = make_float4(tmp[4], tmp[5], tmp[6], tmp[7]);
    }
}

// ============================================================
extern "C" void kernel_launch(void* const* d_in, const int* in_sizes, int n_in,
                              void* d_out, int out_size){
    const float* hidden  = (const float*)d_in[0];
    const float* spec    = (const float*)d_in[1];
    const float* convt_w = (const float*)d_in[2];
    const float* convt_b = (const float*)d_in[3];
    const float* kp_in_w = (const float*)d_in[4];
    const float* kp_in_b = (const float*)d_in[5];
    const float* rb_w1   = (const float*)d_in[6];
    const float* rb_b1   = (const float*)d_in[7];
    const float* rb_w2   = (const float*)d_in[8];
    const float* rb_b2   = (const float*)d_in[9];
    const float* kern_w  = (const float*)d_in[10];
    const float* kern_b  = (const float*)d_in[11];
    const float* bias_w  = (const float*)d_in[12];
    const float* bias_b  = (const float*)d_in[13];
    const float* lvc_w   = (const float*)d_in[14];
    const float* lvc_b   = (const float*)d_in[15];

    cudaFuncSetAttribute(k_pred, cudaFuncAttributeMaxDynamicSharedMemorySize, PRED_SMEM);
    cudaFuncSetAttribute(k_fused<1>,  cudaFuncAttributeMaxDynamicSharedMemorySize, FUSED_SMEM);
    cudaFuncSetAttribute(k_fused<3>,  cudaFuncAttributeMaxDynamicSharedMemorySize, FUSED_SMEM);
    cudaFuncSetAttribute(k_fused<9>,  cudaFuncAttributeMaxDynamicSharedMemorySize, FUSED_SMEM);
    cudaFuncSetAttribute(k_fused<27>, cudaFuncAttributeMaxDynamicSharedMemorySize, FUSED_SMEM);

    k_convT<<<dim3(256, B_), 256>>>(hidden, convt_w, convt_b);
    k_pred<<<dim3(B_, 16), 256, PRED_SMEM>>>(spec, kp_in_w, kp_in_b,
                                             rb_w1, rb_b1, rb_w2, rb_b2);
    // GEMM + fused bias conv
    k_kern_gemm<<<dim3(KC_/128 + 2, (B_*L_)/64), 256>>>(kern_w, kern_b, bias_w, bias_b);

    // four fused dconv+LVC layers
    dim3 dg(L_, B_);
    k_fused<1> <<<dg, 256, FUSED_SMEM>>>(0, lvc_w,        lvc_b,      nullptr);
    k_fused<3> <<<dg, 256, FUSED_SMEM>>>(1, lvc_w + 3072, lvc_b + 32, nullptr);
    k_fused<9> <<<dg, 256, FUSED_SMEM>>>(2, lvc_w + 6144, lvc_b + 64, nullptr);
    k_fused<27><<<dg, 256, FUSED_SMEM>>>(3, lvc_w + 9216, lvc_b + 96, (float*)d_out);
}